// round 4
// baseline (speedup 1.0000x reference)
#include <cuda_runtime.h>
#include <math.h>

#define BB 64
#define SS 512
#define DD 1024
#define HH 1024
#define HH2 512
#define G3 1536
#define GINK 2080
#define SPKD 16
#define NBLK 148
#define NTHR 256

// ---------------- scratch (device globals; no allocation allowed) ----------------
static __device__ float g_xproj[(size_t)2 * SS * BB * G3];   // [dir][t][b][1536]
static __device__ float g_mem[(size_t)SS * BB * HH];          // [t][b][1024]
static __device__ float g_ghp[(size_t)4 * 2 * BB * G3];       // GRU gemm partials
static __device__ float g_gpre[(size_t)4 * BB * 4096];        // gate gemm partials
static __device__ float g_gated[(size_t)BB * HH];
static __device__ float g_h1p[(size_t)16 * BB * HH];          // emo gemm1 partials
static __device__ float g_hln[(size_t)BB * HH];
static __device__ float g_o2p[(size_t)16 * BB * HH];          // emo gemm2 partials
static __device__ unsigned int g_bar;

__global__ void reset_bar_k() { g_bar = 0u; }

// monotonic grid barrier: all NBLK blocks co-resident (grid <= #SMs, occ >= 1)
__device__ __forceinline__ void gsync(unsigned int& bar_id) {
    __syncthreads();
    if (threadIdx.x == 0) {
        __threadfence();
        atomicAdd(&g_bar, 1u);
        bar_id++;
        const unsigned int target = bar_id * NBLK;
        while (*((volatile unsigned int*)&g_bar) < target) {
            __nanosleep(20);
        }
        __threadfence();
    }
    __syncthreads();
}

__device__ __forceinline__ float sigm(float x) { return 1.f / (1.f + expf(-x)); }

// 64x128 tile microkernel step: 16 k's from smem, 4x8 per-thread microtile
__device__ __forceinline__ void mm_fma(float (&acc)[4][8],
                                       const float (*As)[68], const float (*Ws)[132],
                                       int tx, int ty) {
#pragma unroll
    for (int kk = 0; kk < 16; kk++) {
        float4 a  = *(const float4*)&As[kk][ty * 4];
        float4 b0 = *(const float4*)&Ws[kk][tx * 8];
        float4 b1 = *(const float4*)&Ws[kk][tx * 8 + 4];
        float am[4] = {a.x, a.y, a.z, a.w};
        float bn[8] = {b0.x, b0.y, b0.z, b0.w, b1.x, b1.y, b1.z, b1.w};
#pragma unroll
        for (int i = 0; i < 4; i++)
#pragma unroll
            for (int j = 0; j < 8; j++) acc[i][j] += am[i] * bn[j];
    }
}

// ---------------- big GEMM: x_proj = x @ Wih.T + bih (both dirs) ----------------
__global__ __launch_bounds__(256) void xproj_kernel(
    const float* __restrict__ uf,
    const float* __restrict__ Wf_, const float* __restrict__ bf_,
    const float* __restrict__ Wb_, const float* __restrict__ bb_)
{
    __shared__ float As[16][132];
    __shared__ float Ws[16][132];
    const int tid = threadIdx.x;
    const int tx = tid & 15, ty = tid >> 4;
    const int Mbase = blockIdx.x * 128;
    const int Nbase = blockIdx.y * 128;
    const int dir = blockIdx.z;
    const float* W = dir ? Wb_ : Wf_;
    const float* bias = dir ? bb_ : bf_;

    const float* ap[8];
    const float* wp[8];
#pragma unroll
    for (int p = 0; p < 8; p++) {
        int i = tid + p * 256;
        int m = i >> 4, k = i & 15;
        int mg = Mbase + m;
        int tt = mg >> 6, b = mg & 63;
        int srow = dir ? (SS - 1 - tt) : tt;
        ap[p] = uf + ((size_t)b * SS + srow) * DD + k;
        wp[p] = W + (size_t)(Nbase + m) * DD + k;
    }

    float acc[8][8];
#pragma unroll
    for (int i = 0; i < 8; i++)
#pragma unroll
        for (int j = 0; j < 8; j++) acc[i][j] = 0.f;

    for (int kt = 0; kt < DD; kt += 16) {
#pragma unroll
        for (int p = 0; p < 8; p++) {
            int i = tid + p * 256;
            As[i & 15][i >> 4] = ap[p][kt];
            Ws[i & 15][i >> 4] = wp[p][kt];
        }
        __syncthreads();
#pragma unroll
        for (int kk = 0; kk < 16; kk++) {
            float4 a0 = *(const float4*)&As[kk][ty * 8];
            float4 a1 = *(const float4*)&As[kk][ty * 8 + 4];
            float4 b0 = *(const float4*)&Ws[kk][tx * 8];
            float4 b1 = *(const float4*)&Ws[kk][tx * 8 + 4];
            float am[8] = {a0.x, a0.y, a0.z, a0.w, a1.x, a1.y, a1.z, a1.w};
            float bn[8] = {b0.x, b0.y, b0.z, b0.w, b1.x, b1.y, b1.z, b1.w};
#pragma unroll
            for (int i = 0; i < 8; i++)
#pragma unroll
                for (int j = 0; j < 8; j++) acc[i][j] += am[i] * bn[j];
        }
        __syncthreads();
    }

#pragma unroll
    for (int i = 0; i < 8; i++) {
        int mg = Mbase + ty * 8 + i;
        size_t base = ((size_t)dir * SS * BB + mg) * G3 + Nbase + tx * 8;
#pragma unroll
        for (int j = 0; j < 8; j++)
            g_xproj[base + j] = acc[i][j] + bias[Nbase + tx * 8 + j];
    }
}

// ---------------- persistent GRU: 512 steps, 2 grid syncs per step ----------------
__global__ __launch_bounds__(NTHR) void gru_persistent(
    const float* __restrict__ Whh_f, const float* __restrict__ Whh_b,
    const float* __restrict__ bhh_f, const float* __restrict__ bhh_b)
{
    __shared__ float As[16][68];
    __shared__ float Ws[16][132];
    const int tid = threadIdx.x;
    const int tx = tid & 15, ty = tid >> 4;
    const int bx = blockIdx.x;
    unsigned int bar_id = 0;

    const int w = bx;                  // 96 active GEMM work items
    const int dir = w / 48;
    const int nt = (w % 48) >> 2;      // 12 N tiles of 128
    const int ks = w & 3;              // 4 K chunks of 128
    const bool active = (w < 96);
    const float* W = dir ? Whh_b : Whh_f;
    const int Nbase = nt * 128;
    const int k0 = ks * 128;

    for (int t = 0; t < SS; t++) {
        if (active) {
            float acc[4][8];
#pragma unroll
            for (int i = 0; i < 4; i++)
#pragma unroll
                for (int j = 0; j < 8; j++) acc[i][j] = 0.f;

            for (int kt = 0; kt < 128; kt += 16) {
#pragma unroll
                for (int p = 0; p < 4; p++) {
                    int i = tid + p * 256;
                    int m = i >> 4, k = i & 15;
                    int kg = k0 + kt + k;
                    float v = 0.f;
                    if (t > 0) {
                        v = dir ? g_mem[((size_t)(SS - t) * BB + m) * HH + HH2 + kg]
                                : g_mem[((size_t)(t - 1) * BB + m) * HH + kg];
                    }
                    As[k][m] = v;
                }
#pragma unroll
                for (int p = 0; p < 8; p++) {
                    int i = tid + p * 256;
                    int n = i >> 4, k = i & 15;
                    Ws[k][n] = W[(size_t)(Nbase + n) * HH2 + k0 + kt + k];
                }
                __syncthreads();
                mm_fma(acc, As, Ws, tx, ty);
                __syncthreads();
            }
#pragma unroll
            for (int i2 = 0; i2 < 4; i2++) {
                int m = ty * 4 + i2;
                size_t base = (((size_t)ks * 2 + dir) * BB + m) * G3 + Nbase + tx * 8;
#pragma unroll
                for (int j = 0; j < 8; j++) g_ghp[base + j] = acc[i2][j];
            }
        }
        gsync(bar_id);

        // combine: 2*64*512 = 65536 elems
        for (int e = bx * NTHR + tid; e < 2 * BB * HH2; e += NBLK * NTHR) {
            int d2 = e >> 15;
            int b = (e >> 9) & 63;
            int i = e & 511;
            const float* bhh = d2 ? bhh_b : bhh_f;
            float hr = bhh[i], hz = bhh[HH2 + i], hn = bhh[2 * HH2 + i];
#pragma unroll
            for (int q = 0; q < 4; q++) {
                size_t base = (((size_t)q * 2 + d2) * BB + b) * G3;
                hr += g_ghp[base + i];
                hz += g_ghp[base + HH2 + i];
                hn += g_ghp[base + 2 * HH2 + i];
            }
            size_t xb = (((size_t)d2 * SS + t) * BB + b) * G3;
            float xr = g_xproj[xb + i], xz = g_xproj[xb + HH2 + i], xn = g_xproj[xb + 2 * HH2 + i];
            float hp = 0.f;
            if (t > 0)
                hp = d2 ? g_mem[((size_t)(SS - t) * BB + b) * HH + HH2 + i]
                        : g_mem[((size_t)(t - 1) * BB + b) * HH + i];
            float r = sigm(xr + hr);
            float z = sigm(xz + hz);
            float n2 = tanhf(xn + r * hn);
            float h = (1.f - z) * n2 + z * hp;
            if (d2 == 0) g_mem[((size_t)t * BB + b) * HH + i] = h;
            else         g_mem[((size_t)(SS - 1 - t) * BB + b) * HH + HH2 + i] = h;
        }
        gsync(bar_id);
    }
}

// ---------------- emo GEMM phase: M=64,N=1024,K=1024, Ksplit=16 (128 blocks) ----------------
// AMODE 0: A = gated (t>0) or mem[0] (t==0); AMODE 1: A = hln
template <int AMODE>
__device__ __forceinline__ void emo_gemm(int t, const float* __restrict__ W,
                                         float* __restrict__ dst,
                                         float (*As)[68], float (*Ws)[132])
{
    const int tid = threadIdx.x;
    const int tx = tid & 15, ty = tid >> 4;
    const int w = blockIdx.x;
    if (w >= 128) return;
    const int nt = w >> 4;      // 8 N tiles of 128
    const int ks = w & 15;      // 16 K chunks of 64
    const int Nbase = nt * 128;
    const int k0 = ks * 64;

    float acc[4][8];
#pragma unroll
    for (int i = 0; i < 4; i++)
#pragma unroll
        for (int j = 0; j < 8; j++) acc[i][j] = 0.f;

    for (int kt = 0; kt < 64; kt += 16) {
#pragma unroll
        for (int p = 0; p < 4; p++) {
            int i = tid + p * 256;
            int m = i >> 4, k = i & 15;
            int kg = k0 + kt + k;
            float v;
            if (AMODE == 0)
                v = (t == 0) ? g_mem[(size_t)m * HH + kg] : g_gated[(size_t)m * HH + kg];
            else
                v = g_hln[(size_t)m * HH + kg];
            As[k][m] = v;
        }
#pragma unroll
        for (int p = 0; p < 8; p++) {
            int i = tid + p * 256;
            int n = i >> 4, k = i & 15;
            Ws[k][n] = W[(size_t)(Nbase + n) * HH + k0 + kt + k];
        }
        __syncthreads();
        mm_fma(acc, As, Ws, tx, ty);
        __syncthreads();
    }
#pragma unroll
    for (int i2 = 0; i2 < 4; i2++) {
        int m = ty * 4 + i2;
        size_t base = ((size_t)ks * BB + m) * HH + Nbase + tx * 8;
#pragma unroll
        for (int j = 0; j < 8; j++) dst[base + j] = acc[i2][j];
    }
}

// ---------------- gate GEMM phase: M=64,N=4096,K=2080 (pad 2112), Ksplit=4 ----------------
__device__ __forceinline__ void gate_gemm(int t,
    const float* __restrict__ Wf, const float* __restrict__ Wi,
    const float* __restrict__ Wo, const float* __restrict__ Wc,
    const float* __restrict__ outp, const float* __restrict__ spk,
    const float* __restrict__ pos,
    float (*As)[68], float (*Ws)[132])
{
    const int tid = threadIdx.x;
    const int tx = tid & 15, ty = tid >> 4;
    const int w = blockIdx.x;
    if (w >= 128) return;
    const int nt = w >> 2;      // 32 N tiles of 128
    const int ks = w & 3;       // 4 K chunks of 528 (padded to 2112)
    const int Nbase = nt * 128;
    const int gate = Nbase >> 10;
    const float* W = (gate == 0) ? Wf : (gate == 1) ? Wi : (gate == 2) ? Wo : Wc;
    const int wrow = Nbase & 1023;
    const int k0 = ks * 528;

    float acc[4][8];
#pragma unroll
    for (int i = 0; i < 4; i++)
#pragma unroll
        for (int j = 0; j < 8; j++) acc[i][j] = 0.f;

    for (int kt = 0; kt < 528; kt += 16) {
#pragma unroll
        for (int p = 0; p < 4; p++) {
            int i = tid + p * 256;
            int m = i >> 4, k = i & 15;
            int kg = k0 + kt + k;
            float v = 0.f;
            if (kg < 1024)      v = g_mem[((size_t)t * BB + m) * HH + kg];
            else if (kg < 2048) v = outp[((size_t)m * SS + (t - 1)) * HH + (kg - 1024)];
            else if (kg < 2064) v = spk[((size_t)m * SS + t) * SPKD + (kg - 2048)];
            else if (kg < 2080) v = pos[((size_t)m * SS + t) * SPKD + (kg - 2064)];
            As[k][m] = v;
        }
#pragma unroll
        for (int p = 0; p < 8; p++) {
            int i = tid + p * 256;
            int n = i >> 4, k = i & 15;
            int kg = k0 + kt + k;
            Ws[k][n] = (kg < GINK) ? W[(size_t)(wrow + n) * GINK + kg] : 0.f;
        }
        __syncthreads();
        mm_fma(acc, As, Ws, tx, ty);
        __syncthreads();
    }
#pragma unroll
    for (int i2 = 0; i2 < 4; i2++) {
        int m = ty * 4 + i2;
        size_t base = ((size_t)ks * BB + m) * 4096 + Nbase + tx * 8;
#pragma unroll
        for (int j = 0; j < 8; j++) g_gpre[base + j] = acc[i2][j];
    }
}

// ---------------- persistent gating kernel: 512 steps ----------------
__global__ __launch_bounds__(NTHR) void gating_persistent(
    const float* __restrict__ spk, const float* __restrict__ pos,
    const float* __restrict__ Wfw, const float* __restrict__ bfb,
    const float* __restrict__ Wiw, const float* __restrict__ bib,
    const float* __restrict__ Wow, const float* __restrict__ bob,
    const float* __restrict__ Wcw, const float* __restrict__ bcb,
    const float* __restrict__ W1e, const float* __restrict__ b1e,
    const float* __restrict__ gln, const float* __restrict__ beta,
    const float* __restrict__ W2e, const float* __restrict__ b2e,
    float* __restrict__ out)
{
    __shared__ float As[16][68];
    __shared__ float Ws[16][132];
    __shared__ float sred[NTHR];
    __shared__ float stats[2];
    const int tid = threadIdx.x;
    const int bx = blockIdx.x;
    unsigned int bar_id = 0;

    for (int t = 0; t < SS; t++) {
        if (t > 0) {
            // --- phase 1: gate GEMM partials ---
            gate_gemm(t, Wfw, Wiw, Wow, Wcw, out, spk, pos, As, Ws);
            gsync(bar_id);
            // --- phase 2: gate combine -> g_gated ---
            for (int e = bx * NTHR + tid; e < BB * HH; e += NBLK * NTHR) {
                int b = e >> 10, i = e & 1023;
                float f = bfb[i], ig = bib[i], o = bob[i], c = bcb[i];
#pragma unroll
                for (int q = 0; q < 4; q++) {
                    size_t base = ((size_t)q * BB + b) * 4096;
                    f  += g_gpre[base + i];
                    ig += g_gpre[base + 1024 + i];
                    o  += g_gpre[base + 2048 + i];
                    c  += g_gpre[base + 3072 + i];
                }
                float prev = out[((size_t)b * SS + (t - 1)) * HH + i];
                f = sigm(f); ig = sigm(ig); o = sigm(o); c = tanhf(c);
                g_gated[e] = o * tanhf(f * prev + ig * c);
            }
            gsync(bar_id);
        }

        // --- phase 3: emo GEMM1 partials ---
        emo_gemm<0>(t, W1e, g_h1p, As, Ws);
        gsync(bar_id);

        // --- phase 4: LayerNorm + ReLU (64 rows, blocks 0..63) ---
        if (bx < BB) {
            const int b = bx;
            float v[4];
            float lsum = 0.f, lsq = 0.f;
#pragma unroll
            for (int j = 0; j < 4; j++) {
                int i = tid + j * NTHR;
                float x = b1e[i];
#pragma unroll
                for (int q = 0; q < 16; q++) x += g_h1p[((size_t)q * BB + b) * HH + i];
                v[j] = x; lsum += x; lsq += x * x;
            }
            sred[tid] = lsum; __syncthreads();
            for (int s2 = NTHR / 2; s2 > 0; s2 >>= 1) {
                if (tid < s2) sred[tid] += sred[tid + s2];
                __syncthreads();
            }
            if (tid == 0) stats[0] = sred[0] * (1.f / 1024.f);
            __syncthreads();
            sred[tid] = lsq; __syncthreads();
            for (int s2 = NTHR / 2; s2 > 0; s2 >>= 1) {
                if (tid < s2) sred[tid] += sred[tid + s2];
                __syncthreads();
            }
            if (tid == 0) stats[1] = sred[0] * (1.f / 1024.f);
            __syncthreads();
            float mu = stats[0];
            float var = stats[1] - mu * mu;
            float rs = rsqrtf(var + 1e-5f);
#pragma unroll
            for (int j = 0; j < 4; j++) {
                int i = tid + j * NTHR;
                float y = (v[j] - mu) * rs * gln[i] + beta[i];
                g_hln[(size_t)b * HH + i] = y > 0.f ? y : 0.f;
            }
        }
        gsync(bar_id);

        // --- phase 5: emo GEMM2 partials ---
        emo_gemm<1>(t, W2e, g_o2p, As, Ws);
        gsync(bar_id);

        // --- phase 6: finalize out[t] = sum partials + b2e + residual ---
        for (int e = bx * NTHR + tid; e < BB * HH; e += NBLK * NTHR) {
            int b = e >> 10, i = e & 1023;
            float x = b2e[i];
#pragma unroll
            for (int q = 0; q < 16; q++) x += g_o2p[((size_t)q * BB + b) * HH + i];
            float res = (t == 0) ? g_mem[(size_t)b * HH + i] : g_gated[e];
            out[((size_t)b * SS + t) * HH + i] = x + res;
        }
        gsync(bar_id);
    }
}

// ---------------- host launcher: 5 graph nodes total ----------------
extern "C" void kernel_launch(void* const* d_in, const int* in_sizes, int n_in,
                              void* d_out, int out_size)
{
    (void)in_sizes; (void)n_in; (void)out_size;
    const float* uf    = (const float*)d_in[0];
    const float* spk   = (const float*)d_in[1];
    const float* pos   = (const float*)d_in[2];
    const float* Wih_f = (const float*)d_in[3];
    const float* Whh_f = (const float*)d_in[4];
    const float* bih_f = (const float*)d_in[5];
    const float* bhh_f = (const float*)d_in[6];
    const float* Wih_b = (const float*)d_in[7];
    const float* Whh_b = (const float*)d_in[8];
    const float* bih_b = (const float*)d_in[9];
    const float* bhh_b = (const float*)d_in[10];
    const float* Wfw   = (const float*)d_in[11];
    const float* bfb   = (const float*)d_in[12];
    const float* Wiw   = (const float*)d_in[13];
    const float* bib   = (const float*)d_in[14];
    const float* Wow   = (const float*)d_in[15];
    const float* bob   = (const float*)d_in[16];
    const float* Wcw   = (const float*)d_in[17];
    const float* bcb   = (const float*)d_in[18];
    const float* W1e   = (const float*)d_in[19];
    const float* b1e   = (const float*)d_in[20];
    const float* g_ln  = (const float*)d_in[21];
    const float* beta  = (const float*)d_in[22];
    const float* W2e   = (const float*)d_in[23];
    const float* b2e   = (const float*)d_in[24];
    float* out = (float*)d_out;

    // 1) x projections for both GRU directions (parallel, big grid)
    xproj_kernel<<<dim3(256, 12, 2), 256>>>(uf, Wih_f, bih_f, Wih_b, bih_b);

    // 2) persistent bidirectional GRU recurrence
    reset_bar_k<<<1, 1>>>();
    gru_persistent<<<NBLK, NTHR>>>(Whh_f, Whh_b, bhh_f, bhh_b);

    // 3) persistent dialogue gating loop
    reset_bar_k<<<1, 1>>>();
    gating_persistent<<<NBLK, NTHR>>>(spk, pos, Wfw, bfb, Wiw, bib, Wow, bob,
                                      Wcw, bcb, W1e, b1e, g_ln, beta, W2e, b2e, out);
}

// round 6
// speedup vs baseline: 1.2921x; 1.2921x over previous
#include <cuda_runtime.h>
#include <math.h>

#define BB 64
#define SS 512
#define DD 1024
#define HH 1024
#define HH2 512
#define G3 1536
#define GINK 2080
#define SPKD 16
#define NBLK 148
#define NTHR 256

typedef unsigned long long ull;
union F2U { ull u; float2 f; };

#define FMA2(d, a, b) \
    asm("fma.rn.f32x2 %0, %1, %2, %0;" : "+l"(d) : "l"(a), "l"(b))

// ---------------- scratch (device globals; no allocation allowed) ----------------
static __device__ float g_xproj[(size_t)2 * SS * BB * G3];   // [dir][t][b][1536]
static __device__ float g_mem[(size_t)SS * BB * HH];          // [t][b][1024]
static __device__ float g_ghp[(size_t)4 * 2 * BB * G3];       // GRU gemm partials
static __device__ float g_gpre[(size_t)4 * BB * 4096];        // gate gemm partials
static __device__ float g_gated[(size_t)BB * HH];
static __device__ float g_h1p[(size_t)16 * BB * HH];          // emo gemm1 partials
static __device__ float g_hln[(size_t)BB * HH];
static __device__ float g_o2p[(size_t)16 * BB * HH];          // emo gemm2 partials
static __device__ unsigned int g_bar;

__global__ void reset_bar_k() { g_bar = 0u; }

// monotonic grid barrier: all NBLK blocks co-resident (grid <= #SMs, occ >= 1)
__device__ __forceinline__ void gsync(unsigned int& bar_id) {
    __syncthreads();
    if (threadIdx.x == 0) {
        __threadfence();
        atomicAdd(&g_bar, 1u);
        bar_id++;
        const unsigned int target = bar_id * NBLK;
        while (*((volatile unsigned int*)&g_bar) < target) {
            __nanosleep(20);
        }
        __threadfence();
    }
    __syncthreads();
}

__device__ __forceinline__ float sigm(float x) { return 1.f / (1.f + expf(-x)); }

// f32x2 microkernel step: 16 k's, 4 m-rows x 4 n-pairs per thread.
// As2: duplicated A (As2[k][2m]==As2[k][2m+1]), row stride 138 floats.
// Ws2: row stride 134 floats. Thread (tx,ty): m = ty*4+i, n-pair = {2tx+32jp, +1}.
__device__ __forceinline__ void mm_f32x2(ull (&acc)[4][4],
                                         const float (*As2)[138],
                                         const float (*Ws2)[134],
                                         int tx, int ty) {
#pragma unroll
    for (int kk = 0; kk < 16; kk++) {
        ull a2[4], b2[4];
#pragma unroll
        for (int i = 0; i < 4; i++)
            a2[i] = *(const ull*)&As2[kk][(ty * 4 + i) * 2];
#pragma unroll
        for (int jp = 0; jp < 4; jp++)
            b2[jp] = *(const ull*)&Ws2[kk][tx * 2 + jp * 32];
#pragma unroll
        for (int i = 0; i < 4; i++)
#pragma unroll
            for (int jp = 0; jp < 4; jp++)
                FMA2(acc[i][jp], a2[i], b2[jp]);
    }
}

// ---------------- big GEMM: x_proj = x @ Wih.T + bih (both dirs) ----------------
// BM=128, BN=128, BK=16, 256 threads; 8 m-rows x 4 n-pairs per thread via f32x2.
__global__ __launch_bounds__(256) void xproj_kernel(
    const float* __restrict__ uf,
    const float* __restrict__ Wf_, const float* __restrict__ bf_,
    const float* __restrict__ Wb_, const float* __restrict__ bb_)
{
    __shared__ __align__(16) float As2[16][266];
    __shared__ __align__(16) float Ws2[16][134];
    const int tid = threadIdx.x;
    const int tx = tid & 15, ty = tid >> 4;
    const int Mbase = blockIdx.x * 128;
    const int Nbase = blockIdx.y * 128;
    const int dir = blockIdx.z;
    const float* W = dir ? Wb_ : Wf_;
    const float* bias = dir ? bb_ : bf_;

    const float* ap[8];
    const float* wp[8];
#pragma unroll
    for (int p = 0; p < 8; p++) {
        int i = tid + p * 256;
        int m = i >> 4, k = i & 15;
        int mg = Mbase + m;
        int tt = mg >> 6, b = mg & 63;
        int srow = dir ? (SS - 1 - tt) : tt;
        ap[p] = uf + ((size_t)b * SS + srow) * DD + k;
        wp[p] = W + (size_t)(Nbase + m) * DD + k;
    }

    ull acc[8][4];
#pragma unroll
    for (int i = 0; i < 8; i++)
#pragma unroll
        for (int j = 0; j < 4; j++) acc[i][j] = 0ull;

    for (int kt = 0; kt < DD; kt += 16) {
#pragma unroll
        for (int p = 0; p < 8; p++) {
            int i = tid + p * 256;
            int m = i >> 4, k = i & 15;
            float v = ap[p][kt];
            *(float2*)&As2[k][2 * m] = make_float2(v, v);
            Ws2[k][m] = wp[p][kt];
        }
        __syncthreads();
#pragma unroll
        for (int kk = 0; kk < 16; kk++) {
            ull a2[8], b2[4];
#pragma unroll
            for (int i = 0; i < 8; i++)
                a2[i] = *(const ull*)&As2[kk][(ty * 8 + i) * 2];
#pragma unroll
            for (int jp = 0; jp < 4; jp++)
                b2[jp] = *(const ull*)&Ws2[kk][tx * 2 + jp * 32];
#pragma unroll
            for (int i = 0; i < 8; i++)
#pragma unroll
                for (int jp = 0; jp < 4; jp++)
                    FMA2(acc[i][jp], a2[i], b2[jp]);
        }
        __syncthreads();
    }

#pragma unroll
    for (int i = 0; i < 8; i++) {
        int mg = Mbase + ty * 8 + i;
        size_t rowb = ((size_t)dir * SS * BB + mg) * G3;
#pragma unroll
        for (int jp = 0; jp < 4; jp++) {
            int col = Nbase + 2 * tx + 32 * jp;
            F2U u; u.u = acc[i][jp];
            u.f.x += bias[col];
            u.f.y += bias[col + 1];
            *(float2*)&g_xproj[rowb + col] = u.f;
        }
    }
}

// ---------------- persistent GRU: 512 steps, 2 grid syncs per step ----------------
__global__ __launch_bounds__(NTHR) void gru_persistent(
    const float* __restrict__ Whh_f, const float* __restrict__ Whh_b,
    const float* __restrict__ bhh_f, const float* __restrict__ bhh_b)
{
    __shared__ __align__(16) float As2[16][138];
    __shared__ __align__(16) float Ws2[16][134];
    const int tid = threadIdx.x;
    const int tx = tid & 15, ty = tid >> 4;
    const int bx = blockIdx.x;
    unsigned int bar_id = 0;

    const int w = bx;                  // 96 active GEMM work items
    const int dir = w / 48;
    const int nt = (w % 48) >> 2;      // 12 N tiles of 128
    const int ks = w & 3;              // 4 K chunks of 128
    const bool active = (w < 96);
    const float* W = dir ? Whh_b : Whh_f;
    const int Nbase = nt * 128;
    const int k0 = ks * 128;

    for (int t = 0; t < SS; t++) {
        if (active) {
            ull acc[4][4];
#pragma unroll
            for (int i = 0; i < 4; i++)
#pragma unroll
                for (int j = 0; j < 4; j++) acc[i][j] = 0ull;

            for (int kt = 0; kt < 128; kt += 16) {
#pragma unroll
                for (int p = 0; p < 4; p++) {
                    int i = tid + p * 256;
                    int m = i >> 4, k = i & 15;
                    int kg = k0 + kt + k;
                    float v = 0.f;
                    if (t > 0) {
                        v = dir ? g_mem[((size_t)(SS - t) * BB + m) * HH + HH2 + kg]
                                : g_mem[((size_t)(t - 1) * BB + m) * HH + kg];
                    }
                    *(float2*)&As2[k][2 * m] = make_float2(v, v);
                }
#pragma unroll
                for (int p = 0; p < 8; p++) {
                    int i = tid + p * 256;
                    int n = i >> 4, k = i & 15;
                    Ws2[k][n] = W[(size_t)(Nbase + n) * HH2 + k0 + kt + k];
                }
                __syncthreads();
                mm_f32x2(acc, As2, Ws2, tx, ty);
                __syncthreads();
            }
#pragma unroll
            for (int i2 = 0; i2 < 4; i2++) {
                int m = ty * 4 + i2;
                size_t rowb = (((size_t)ks * 2 + dir) * BB + m) * G3;
#pragma unroll
                for (int jp = 0; jp < 4; jp++) {
                    int col = Nbase + 2 * tx + 32 * jp;
                    F2U u; u.u = acc[i2][jp];
                    *(float2*)&g_ghp[rowb + col] = u.f;
                }
            }
        }
        gsync(bar_id);

        // combine: 2*64*512 = 65536 elems
        for (int e = bx * NTHR + tid; e < 2 * BB * HH2; e += NBLK * NTHR) {
            int d2 = e >> 15;
            int b = (e >> 9) & 63;
            int i = e & 511;
            const float* bhh = d2 ? bhh_b : bhh_f;
            float hr = bhh[i], hz = bhh[HH2 + i], hn = bhh[2 * HH2 + i];
#pragma unroll
            for (int q = 0; q < 4; q++) {
                size_t base = (((size_t)q * 2 + d2) * BB + b) * G3;
                hr += g_ghp[base + i];
                hz += g_ghp[base + HH2 + i];
                hn += g_ghp[base + 2 * HH2 + i];
            }
            size_t xb = (((size_t)d2 * SS + t) * BB + b) * G3;
            float xr = g_xproj[xb + i], xz = g_xproj[xb + HH2 + i], xn = g_xproj[xb + 2 * HH2 + i];
            float hp = 0.f;
            if (t > 0)
                hp = d2 ? g_mem[((size_t)(SS - t) * BB + b) * HH + HH2 + i]
                        : g_mem[((size_t)(t - 1) * BB + b) * HH + i];
            float r = sigm(xr + hr);
            float z = sigm(xz + hz);
            float n2 = tanhf(xn + r * hn);
            float h = (1.f - z) * n2 + z * hp;
            if (d2 == 0) g_mem[((size_t)t * BB + b) * HH + i] = h;
            else         g_mem[((size_t)(SS - 1 - t) * BB + b) * HH + HH2 + i] = h;
        }
        gsync(bar_id);
    }
}

// ---------------- emo GEMM phase: M=64,N=1024,K=1024, Ksplit=16 (128 blocks) ----------------
template <int AMODE>
__device__ __forceinline__ void emo_gemm(int t, const float* __restrict__ W,
                                         float* __restrict__ dst,
                                         float (*As2)[138], float (*Ws2)[134])
{
    const int tid = threadIdx.x;
    const int tx = tid & 15, ty = tid >> 4;
    const int w = blockIdx.x;
    if (w >= 128) return;
    const int nt = w >> 4;      // 8 N tiles of 128
    const int ks = w & 15;      // 16 K chunks of 64
    const int Nbase = nt * 128;
    const int k0 = ks * 64;

    ull acc[4][4];
#pragma unroll
    for (int i = 0; i < 4; i++)
#pragma unroll
        for (int j = 0; j < 4; j++) acc[i][j] = 0ull;

    for (int kt = 0; kt < 64; kt += 16) {
#pragma unroll
        for (int p = 0; p < 4; p++) {
            int i = tid + p * 256;
            int m = i >> 4, k = i & 15;
            int kg = k0 + kt + k;
            float v;
            if (AMODE == 0)
                v = (t == 0) ? g_mem[(size_t)m * HH + kg] : g_gated[(size_t)m * HH + kg];
            else
                v = g_hln[(size_t)m * HH + kg];
            *(float2*)&As2[k][2 * m] = make_float2(v, v);
        }
#pragma unroll
        for (int p = 0; p < 8; p++) {
            int i = tid + p * 256;
            int n = i >> 4, k = i & 15;
            Ws2[k][n] = W[(size_t)(Nbase + n) * HH + k0 + kt + k];
        }
        __syncthreads();
        mm_f32x2(acc, (const float (*)[138])As2, (const float (*)[134])Ws2, tx, ty);
        __syncthreads();
    }
#pragma unroll
    for (int i2 = 0; i2 < 4; i2++) {
        int m = ty * 4 + i2;
        size_t rowb = ((size_t)ks * BB + m) * HH;
#pragma unroll
        for (int jp = 0; jp < 4; jp++) {
            int col = Nbase + 2 * tx + 32 * jp;
            F2U u; u.u = acc[i2][jp];
            *(float2*)&dst[rowb + col] = u.f;
        }
    }
}

// ---------------- gate GEMM phase: M=64,N=4096,K=2080 (pad 2112), Ksplit=4 ----------------
__device__ __forceinline__ void gate_gemm(int t,
    const float* __restrict__ Wf, const float* __restrict__ Wi,
    const float* __restrict__ Wo, const float* __restrict__ Wc,
    const float* __restrict__ outp, const float* __restrict__ spk,
    const float* __restrict__ pos,
    float (*As2)[138], float (*Ws2)[134])
{
    const int tid = threadIdx.x;
    const int tx = tid & 15, ty = tid >> 4;
    const int w = blockIdx.x;
    if (w >= 128) return;
    const int nt = w >> 2;      // 32 N tiles of 128
    const int ks = w & 3;       // 4 K chunks of 528 (padded to 2112)
    const int Nbase = nt * 128;
    const int gate = Nbase >> 10;
    const float* W = (gate == 0) ? Wf : (gate == 1) ? Wi : (gate == 2) ? Wo : Wc;
    const int wrow = Nbase & 1023;
    const int k0 = ks * 528;

    ull acc[4][4];
#pragma unroll
    for (int i = 0; i < 4; i++)
#pragma unroll
        for (int j = 0; j < 4; j++) acc[i][j] = 0ull;

    for (int kt = 0; kt < 528; kt += 16) {
#pragma unroll
        for (int p = 0; p < 4; p++) {
            int i = tid + p * 256;
            int m = i >> 4, k = i & 15;
            int kg = k0 + kt + k;
            float v = 0.f;
            if (kg < 1024)      v = g_mem[((size_t)t * BB + m) * HH + kg];
            else if (kg < 2048) v = outp[((size_t)m * SS + (t - 1)) * HH + (kg - 1024)];
            else if (kg < 2064) v = spk[((size_t)m * SS + t) * SPKD + (kg - 2048)];
            else if (kg < 2080) v = pos[((size_t)m * SS + t) * SPKD + (kg - 2064)];
            *(float2*)&As2[k][2 * m] = make_float2(v, v);
        }
#pragma unroll
        for (int p = 0; p < 8; p++) {
            int i = tid + p * 256;
            int n = i >> 4, k = i & 15;
            int kg = k0 + kt + k;
            Ws2[k][n] = (kg < GINK) ? W[(size_t)(wrow + n) * GINK + kg] : 0.f;
        }
        __syncthreads();
        mm_f32x2(acc, (const float (*)[138])As2, (const float (*)[134])Ws2, tx, ty);
        __syncthreads();
    }
#pragma unroll
    for (int i2 = 0; i2 < 4; i2++) {
        int m = ty * 4 + i2;
        size_t rowb = ((size_t)ks * BB + m) * 4096;
#pragma unroll
        for (int jp = 0; jp < 4; jp++) {
            int col = Nbase + 2 * tx + 32 * jp;
            F2U u; u.u = acc[i2][jp];
            *(float2*)&g_gpre[rowb + col] = u.f;
        }
    }
}

// ---------------- persistent gating kernel: 512 steps ----------------
__global__ __launch_bounds__(NTHR) void gating_persistent(
    const float* __restrict__ spk, const float* __restrict__ pos,
    const float* __restrict__ Wfw, const float* __restrict__ bfb,
    const float* __restrict__ Wiw, const float* __restrict__ bib,
    const float* __restrict__ Wow, const float* __restrict__ bob,
    const float* __restrict__ Wcw, const float* __restrict__ bcb,
    const float* __restrict__ W1e, const float* __restrict__ b1e,
    const float* __restrict__ gln, const float* __restrict__ beta,
    const float* __restrict__ W2e, const float* __restrict__ b2e,
    float* __restrict__ out)
{
    __shared__ __align__(16) float As2[16][138];
    __shared__ __align__(16) float Ws2[16][134];
    __shared__ float sred[NTHR];
    __shared__ float stats[2];
    const int tid = threadIdx.x;
    const int bx = blockIdx.x;
    unsigned int bar_id = 0;

    for (int t = 0; t < SS; t++) {
        if (t > 0) {
            // --- phase 1: gate GEMM partials ---
            gate_gemm(t, Wfw, Wiw, Wow, Wcw, out, spk, pos, As2, Ws2);
            gsync(bar_id);
            // --- phase 2: gate combine -> g_gated ---
            for (int e = bx * NTHR + tid; e < BB * HH; e += NBLK * NTHR) {
                int b = e >> 10, i = e & 1023;
                float f = bfb[i], ig = bib[i], o = bob[i], c = bcb[i];
#pragma unroll
                for (int q = 0; q < 4; q++) {
                    size_t base = ((size_t)q * BB + b) * 4096;
                    f  += g_gpre[base + i];
                    ig += g_gpre[base + 1024 + i];
                    o  += g_gpre[base + 2048 + i];
                    c  += g_gpre[base + 3072 + i];
                }
                float prev = out[((size_t)b * SS + (t - 1)) * HH + i];
                f = sigm(f); ig = sigm(ig); o = sigm(o); c = tanhf(c);
                g_gated[e] = o * tanhf(f * prev + ig * c);
            }
            gsync(bar_id);
        }

        // --- phase 3: emo GEMM1 partials ---
        emo_gemm<0>(t, W1e, g_h1p, As2, Ws2);
        gsync(bar_id);

        // --- phase 4: LayerNorm + ReLU (64 rows, blocks 0..63) ---
        if (bx < BB) {
            const int b = bx;
            float v[4];
            float lsum = 0.f, lsq = 0.f;
#pragma unroll
            for (int j = 0; j < 4; j++) {
                int i = tid + j * NTHR;
                float x = b1e[i];
#pragma unroll
                for (int q = 0; q < 16; q++) x += g_h1p[((size_t)q * BB + b) * HH + i];
                v[j] = x; lsum += x; lsq += x * x;
            }
            sred[tid] = lsum; __syncthreads();
            for (int s2 = NTHR / 2; s2 > 0; s2 >>= 1) {
                if (tid < s2) sred[tid] += sred[tid + s2];
                __syncthreads();
            }
            if (tid == 0) stats[0] = sred[0] * (1.f / 1024.f);
            __syncthreads();
            sred[tid] = lsq; __syncthreads();
            for (int s2 = NTHR / 2; s2 > 0; s2 >>= 1) {
                if (tid < s2) sred[tid] += sred[tid + s2];
                __syncthreads();
            }
            if (tid == 0) stats[1] = sred[0] * (1.f / 1024.f);
            __syncthreads();
            float mu = stats[0];
            float var = stats[1] - mu * mu;
            float rs = rsqrtf(var + 1e-5f);
#pragma unroll
            for (int j = 0; j < 4; j++) {
                int i = tid + j * NTHR;
                float y = (v[j] - mu) * rs * gln[i] + beta[i];
                g_hln[(size_t)b * HH + i] = y > 0.f ? y : 0.f;
            }
        }
        gsync(bar_id);

        // --- phase 5: emo GEMM2 partials ---
        emo_gemm<1>(t, W2e, g_o2p, As2, Ws2);
        gsync(bar_id);

        // --- phase 6: finalize out[t] = sum partials + b2e + residual ---
        for (int e = bx * NTHR + tid; e < BB * HH; e += NBLK * NTHR) {
            int b = e >> 10, i = e & 1023;
            float x = b2e[i];
#pragma unroll
            for (int q = 0; q < 16; q++) x += g_o2p[((size_t)q * BB + b) * HH + i];
            float res = (t == 0) ? g_mem[(size_t)b * HH + i] : g_gated[e];
            out[((size_t)b * SS + t) * HH + i] = x + res;
        }
        gsync(bar_id);
    }
}

// ---------------- host launcher: 5 graph nodes total ----------------
extern "C" void kernel_launch(void* const* d_in, const int* in_sizes, int n_in,
                              void* d_out, int out_size)
{
    (void)in_sizes; (void)n_in; (void)out_size;
    const float* uf    = (const float*)d_in[0];
    const float* spk   = (const float*)d_in[1];
    const float* pos   = (const float*)d_in[2];
    const float* Wih_f = (const float*)d_in[3];
    const float* Whh_f = (const float*)d_in[4];
    const float* bih_f = (const float*)d_in[5];
    const float* bhh_f = (const float*)d_in[6];
    const float* Wih_b = (const float*)d_in[7];
    const float* Whh_b = (const float*)d_in[8];
    const float* bih_b = (const float*)d_in[9];
    const float* bhh_b = (const float*)d_in[10];
    const float* Wfw   = (const float*)d_in[11];
    const float* bfb   = (const float*)d_in[12];
    const float* Wiw   = (const float*)d_in[13];
    const float* bib   = (const float*)d_in[14];
    const float* Wow   = (const float*)d_in[15];
    const float* bob   = (const float*)d_in[16];
    const float* Wcw   = (const float*)d_in[17];
    const float* bcb   = (const float*)d_in[18];
    const float* W1e   = (const float*)d_in[19];
    const float* b1e   = (const float*)d_in[20];
    const float* g_ln  = (const float*)d_in[21];
    const float* beta  = (const float*)d_in[22];
    const float* W2e   = (const float*)d_in[23];
    const float* b2e   = (const float*)d_in[24];
    float* out = (float*)d_out;

    // 1) x projections for both GRU directions (parallel, big grid)
    xproj_kernel<<<dim3(256, 12, 2), 256>>>(uf, Wih_f, bih_f, Wih_b, bih_b);

    // 2) persistent bidirectional GRU recurrence
    reset_bar_k<<<1, 1>>>();
    gru_persistent<<<NBLK, NTHR>>>(Whh_f, Whh_b, bhh_f, bhh_b);

    // 3) persistent dialogue gating loop
    reset_bar_k<<<1, 1>>>();
    gating_persistent<<<NBLK, NTHR>>>(spk, pos, Wfw, bfb, Wiw, bib, Wow, bob,
                                      Wcw, bcb, W1e, b1e, g_ln, beta, W2e, b2e, out);
}

// round 7
// speedup vs baseline: 2.2478x; 1.7396x over previous
#include <cuda_runtime.h>
#include <math.h>

#define BB 64
#define SS 512
#define DD 1024
#define HH 1024
#define HH2 512
#define G3 1536
#define GINK 2080
#define SPKD 16
#define NBLK 148
#define NTHR 256

typedef unsigned long long ull;
union F2U { ull u; float2 f; };

#define FMA2(d, a, b) \
    asm("fma.rn.f32x2 %0, %1, %2, %0;" : "+l"(d) : "l"(a), "l"(b))

__device__ __forceinline__ ull dup2(float a) {
    ull d;
    asm("mov.b64 %0, {%1, %1};" : "=l"(d) : "f"(a));
    return d;
}

// K-split counts
#define KS_GATE 9     // chunk 240 (15 tiles), K padded 2160
#define KS_GRU  11    // chunk 48 (3 tiles), last chunk 32
#define KS_EMO  32    // chunk 32 (2 tiles)

// ---------------- scratch (device globals; no allocation allowed) ----------------
static __device__ float g_xproj[(size_t)2 * SS * BB * G3];   // [dir][t][b][1536]
static __device__ float g_mem[(size_t)SS * BB * HH];          // [t][b][1024]
static __device__ float g_ghp[(size_t)KS_GRU * 2 * BB * G3];  // GRU gemm partials
static __device__ float g_gpre[(size_t)KS_GATE * BB * 4096];  // gate gemm partials
static __device__ float g_gated[(size_t)BB * HH];
static __device__ float g_h1p[(size_t)KS_EMO * BB * HH];      // emo gemm1 partials
static __device__ float g_hln[(size_t)BB * HH];
static __device__ float g_o2p[(size_t)KS_EMO * BB * HH];      // emo gemm2 partials
static __device__ unsigned int g_bar;

__global__ void reset_bar_k() { g_bar = 0u; }

// monotonic grid barrier: all NBLK blocks co-resident (grid <= #SMs, occ >= 1)
__device__ __forceinline__ void gsync(unsigned int& bar_id) {
    __syncthreads();
    if (threadIdx.x == 0) {
        __threadfence();
        atomicAdd(&g_bar, 1u);
        bar_id++;
        const unsigned int target = bar_id * NBLK;
        while (*((volatile unsigned int*)&g_bar) < target) {
            __nanosleep(20);
        }
        __threadfence();
    }
    __syncthreads();
}

__device__ __forceinline__ float sigm(float x) { return 1.f / (1.f + expf(-x)); }

// ---- M=64 x N=256 microkernel: 8m x 4 n-pairs per thread, broadcast-A ----
// As[16][68] scalar A (As[k][m]); Ws[16][260] (Ws[k][n], n<256).
// tx = tid & 31, ty = tid >> 5; m = ty*8+i; col = 2*tx + 64*jp.
__device__ __forceinline__ void mk64(ull (&acc)[8][4],
                                     const float (*As)[68],
                                     const float (*Ws)[260],
                                     int tx, int ty) {
#pragma unroll
    for (int kk = 0; kk < 16; kk++) {
        float4 alo = *(const float4*)&As[kk][ty * 8];
        float4 ahi = *(const float4*)&As[kk][ty * 8 + 4];
        ull a2[8];
        a2[0] = dup2(alo.x); a2[1] = dup2(alo.y);
        a2[2] = dup2(alo.z); a2[3] = dup2(alo.w);
        a2[4] = dup2(ahi.x); a2[5] = dup2(ahi.y);
        a2[6] = dup2(ahi.z); a2[7] = dup2(ahi.w);
        ull b2[4];
#pragma unroll
        for (int jp = 0; jp < 4; jp++)
            b2[jp] = *(const ull*)&Ws[kk][2 * tx + 64 * jp];
#pragma unroll
        for (int i = 0; i < 8; i++)
#pragma unroll
            for (int jp = 0; jp < 4; jp++)
                FMA2(acc[i][jp], a2[i], b2[jp]);
    }
}

// ---------------- big GEMM: x_proj = x @ Wih.T + bih (both dirs) ----------------
// BM=128, BN=128, BK=16; 8m x 4 n-pairs, broadcast-A + register-staged prefetch.
__global__ __launch_bounds__(256) void xproj_kernel(
    const float* __restrict__ uf,
    const float* __restrict__ Wf_, const float* __restrict__ bf_,
    const float* __restrict__ Wb_, const float* __restrict__ bb_)
{
    __shared__ __align__(16) float As[16][132];
    __shared__ __align__(16) float Ws[16][132];
    const int tid = threadIdx.x;
    const int tx = tid & 15, ty = tid >> 4;
    const int Mbase = blockIdx.x * 128;
    const int Nbase = blockIdx.y * 128;
    const int dir = blockIdx.z;
    const float* W = dir ? Wb_ : Wf_;
    const float* bias = dir ? bb_ : bf_;

    const float* ap[8];
    const float* wp[8];
#pragma unroll
    for (int p = 0; p < 8; p++) {
        int i = tid + p * 256;
        int m = i >> 4, k = i & 15;
        int mg = Mbase + m;
        int tt = mg >> 6, b = mg & 63;
        int srow = dir ? (SS - 1 - tt) : tt;
        ap[p] = uf + ((size_t)b * SS + srow) * DD + k;
        wp[p] = W + (size_t)(Nbase + m) * DD + k;
    }

    ull acc[8][4];
#pragma unroll
    for (int i = 0; i < 8; i++)
#pragma unroll
        for (int j = 0; j < 4; j++) acc[i][j] = 0ull;

    float va[8], vw[8];
#pragma unroll
    for (int p = 0; p < 8; p++) { va[p] = ap[p][0]; vw[p] = wp[p][0]; }

    for (int kt = 0; kt < DD; kt += 16) {
        __syncthreads();
#pragma unroll
        for (int p = 0; p < 8; p++) {
            int i = tid + p * 256;
            As[i & 15][i >> 4] = va[p];
            Ws[i & 15][i >> 4] = vw[p];
        }
        __syncthreads();
        if (kt + 16 < DD) {
#pragma unroll
            for (int p = 0; p < 8; p++) {
                va[p] = ap[p][kt + 16];
                vw[p] = wp[p][kt + 16];
            }
        }
        // compute: 8m x 4np, half-warp broadcast A
#pragma unroll
        for (int kk = 0; kk < 16; kk++) {
            float4 alo = *(const float4*)&As[kk][ty * 8];
            float4 ahi = *(const float4*)&As[kk][ty * 8 + 4];
            ull a2[8];
            a2[0] = dup2(alo.x); a2[1] = dup2(alo.y);
            a2[2] = dup2(alo.z); a2[3] = dup2(alo.w);
            a2[4] = dup2(ahi.x); a2[5] = dup2(ahi.y);
            a2[6] = dup2(ahi.z); a2[7] = dup2(ahi.w);
            ull b2[4];
#pragma unroll
            for (int jp = 0; jp < 4; jp++)
                b2[jp] = *(const ull*)&Ws[kk][2 * tx + 32 * jp];
#pragma unroll
            for (int i = 0; i < 8; i++)
#pragma unroll
                for (int jp = 0; jp < 4; jp++)
                    FMA2(acc[i][jp], a2[i], b2[jp]);
        }
    }

#pragma unroll
    for (int i = 0; i < 8; i++) {
        int mg = Mbase + ty * 8 + i;
        size_t rowb = ((size_t)dir * SS * BB + mg) * G3;
#pragma unroll
        for (int jp = 0; jp < 4; jp++) {
            int col = Nbase + 2 * tx + 32 * jp;
            F2U u; u.u = acc[i][jp];
            u.f.x += bias[col];
            u.f.y += bias[col + 1];
            *(float2*)&g_xproj[rowb + col] = u.f;
        }
    }
}

// ---------------- persistent GRU: 512 steps, 2 grid syncs per step ----------------
// GEMM: per dir N=1536 (6 tiles of 256), K=512 (11 chunks of 48, last 32) -> 132 blocks
__global__ __launch_bounds__(NTHR, 1) void gru_persistent(
    const float* __restrict__ Whh_f, const float* __restrict__ Whh_b,
    const float* __restrict__ bhh_f, const float* __restrict__ bhh_b)
{
    __shared__ __align__(16) float As[16][68];
    __shared__ __align__(16) float Ws[16][260];
    const int tid = threadIdx.x;
    const int tx = tid & 31, ty = tid >> 5;
    const int bx = blockIdx.x;
    unsigned int bar_id = 0;

    const int w = bx;
    const bool active = (w < 2 * 6 * KS_GRU);
    const int dir = w / (6 * KS_GRU);
    const int rem = w % (6 * KS_GRU);
    const int nt = rem / KS_GRU;
    const int ks = rem % KS_GRU;
    const float* W = dir ? Whh_b : Whh_f;
    const int Nbase = nt * 256;
    const int k0 = ks * 48;
    const int k1 = (k0 + 48 < HH2) ? (k0 + 48) : HH2;

    for (int t = 0; t < SS; t++) {
        if (active) {
            ull acc[8][4];
#pragma unroll
            for (int i = 0; i < 8; i++)
#pragma unroll
                for (int j = 0; j < 4; j++) acc[i][j] = 0ull;

            float va[4], vw[16];
            // prologue stage: tile k0
#pragma unroll
            for (int p = 0; p < 4; p++) {
                int i = tid + p * 256;
                int m = i >> 4, kg = k0 + (i & 15);
                float v = 0.f;
                if (t > 0)
                    v = dir ? g_mem[((size_t)(SS - t) * BB + m) * HH + HH2 + kg]
                            : g_mem[((size_t)(t - 1) * BB + m) * HH + kg];
                va[p] = v;
            }
#pragma unroll
            for (int p = 0; p < 16; p++) {
                int i = tid + p * 256;
                int n = i >> 4, kg = k0 + (i & 15);
                vw[p] = W[(size_t)(Nbase + n) * HH2 + kg];
            }

            for (int kt = k0; kt < k1; kt += 16) {
                __syncthreads();
#pragma unroll
                for (int p = 0; p < 4; p++) {
                    int i = tid + p * 256;
                    As[i & 15][i >> 4] = va[p];
                }
#pragma unroll
                for (int p = 0; p < 16; p++) {
                    int i = tid + p * 256;
                    Ws[i & 15][i >> 4] = vw[p];
                }
                __syncthreads();
                if (kt + 16 < k1) {
#pragma unroll
                    for (int p = 0; p < 4; p++) {
                        int i = tid + p * 256;
                        int m = i >> 4, kg = kt + 16 + (i & 15);
                        float v = 0.f;
                        if (t > 0)
                            v = dir ? g_mem[((size_t)(SS - t) * BB + m) * HH + HH2 + kg]
                                    : g_mem[((size_t)(t - 1) * BB + m) * HH + kg];
                        va[p] = v;
                    }
#pragma unroll
                    for (int p = 0; p < 16; p++) {
                        int i = tid + p * 256;
                        int n = i >> 4, kg = kt + 16 + (i & 15);
                        vw[p] = W[(size_t)(Nbase + n) * HH2 + kg];
                    }
                }
                mk64(acc, As, Ws, tx, ty);
            }
#pragma unroll
            for (int i2 = 0; i2 < 8; i2++) {
                int m = ty * 8 + i2;
                size_t rowb = (((size_t)ks * 2 + dir) * BB + m) * G3;
#pragma unroll
                for (int jp = 0; jp < 4; jp++) {
                    int col = Nbase + 2 * tx + 64 * jp;
                    F2U u; u.u = acc[i2][jp];
                    *(float2*)&g_ghp[rowb + col] = u.f;
                }
            }
        }
        gsync(bar_id);

        // combine: 2*64*512 = 65536 elems
        for (int e = bx * NTHR + tid; e < 2 * BB * HH2; e += NBLK * NTHR) {
            int d2 = e >> 15;
            int b = (e >> 9) & 63;
            int i = e & 511;
            const float* bhh = d2 ? bhh_b : bhh_f;
            float hr = bhh[i], hz = bhh[HH2 + i], hn = bhh[2 * HH2 + i];
#pragma unroll
            for (int q = 0; q < KS_GRU; q++) {
                size_t base = (((size_t)q * 2 + d2) * BB + b) * G3;
                hr += g_ghp[base + i];
                hz += g_ghp[base + HH2 + i];
                hn += g_ghp[base + 2 * HH2 + i];
            }
            size_t xb = (((size_t)d2 * SS + t) * BB + b) * G3;
            float xr = g_xproj[xb + i], xz = g_xproj[xb + HH2 + i], xn = g_xproj[xb + 2 * HH2 + i];
            float hp = 0.f;
            if (t > 0)
                hp = d2 ? g_mem[((size_t)(SS - t) * BB + b) * HH + HH2 + i]
                        : g_mem[((size_t)(t - 1) * BB + b) * HH + i];
            float r = sigm(xr + hr);
            float z = sigm(xz + hz);
            float n2 = tanhf(xn + r * hn);
            float h = (1.f - z) * n2 + z * hp;
            if (d2 == 0) g_mem[((size_t)t * BB + b) * HH + i] = h;
            else         g_mem[((size_t)(SS - 1 - t) * BB + b) * HH + HH2 + i] = h;
        }
        gsync(bar_id);
    }
}

// ---------------- emo GEMM phase: N=1024 (4 tiles of 256), K=1024 (32 chunks of 32) ----------------
template <int AMODE>
__device__ __forceinline__ void emo_gemm(int t, const float* __restrict__ W,
                                         float* __restrict__ dst,
                                         float (*As)[68], float (*Ws)[260],
                                         int tx, int ty)
{
    const int tid = threadIdx.x;
    const int w = blockIdx.x;
    if (w >= 4 * KS_EMO) return;
    const int nt = w >> 5;
    const int ks = w & 31;
    const int Nbase = nt * 256;
    const int k0 = ks * 32;

    ull acc[8][4];
#pragma unroll
    for (int i = 0; i < 8; i++)
#pragma unroll
        for (int j = 0; j < 4; j++) acc[i][j] = 0ull;

    float va[4], vw[16];
#pragma unroll
    for (int p = 0; p < 4; p++) {
        int i = tid + p * 256;
        int m = i >> 4, kg = k0 + (i & 15);
        float v;
        if (AMODE == 0)
            v = (t == 0) ? g_mem[(size_t)m * HH + kg] : g_gated[(size_t)m * HH + kg];
        else
            v = g_hln[(size_t)m * HH + kg];
        va[p] = v;
    }
#pragma unroll
    for (int p = 0; p < 16; p++) {
        int i = tid + p * 256;
        int n = i >> 4, kg = k0 + (i & 15);
        vw[p] = W[(size_t)(Nbase + n) * HH + kg];
    }

    for (int kt = k0; kt < k0 + 32; kt += 16) {
        __syncthreads();
#pragma unroll
        for (int p = 0; p < 4; p++) {
            int i = tid + p * 256;
            As[i & 15][i >> 4] = va[p];
        }
#pragma unroll
        for (int p = 0; p < 16; p++) {
            int i = tid + p * 256;
            Ws[i & 15][i >> 4] = vw[p];
        }
        __syncthreads();
        if (kt + 16 < k0 + 32) {
#pragma unroll
            for (int p = 0; p < 4; p++) {
                int i = tid + p * 256;
                int m = i >> 4, kg = kt + 16 + (i & 15);
                float v;
                if (AMODE == 0)
                    v = (t == 0) ? g_mem[(size_t)m * HH + kg] : g_gated[(size_t)m * HH + kg];
                else
                    v = g_hln[(size_t)m * HH + kg];
                va[p] = v;
            }
#pragma unroll
            for (int p = 0; p < 16; p++) {
                int i = tid + p * 256;
                int n = i >> 4, kg = kt + 16 + (i & 15);
                vw[p] = W[(size_t)(Nbase + n) * HH + kg];
            }
        }
        mk64(acc, (const float (*)[68])As, (const float (*)[260])Ws, tx, ty);
    }
#pragma unroll
    for (int i2 = 0; i2 < 8; i2++) {
        int m = ty * 8 + i2;
        size_t rowb = ((size_t)ks * BB + m) * HH;
#pragma unroll
        for (int jp = 0; jp < 4; jp++) {
            int col = Nbase + 2 * tx + 64 * jp;
            F2U u; u.u = acc[i2][jp];
            *(float2*)&dst[rowb + col] = u.f;
        }
    }
}

// ---------------- gate GEMM phase: N=4096 (16 tiles of 256), K=2080 pad 2160 (9 chunks of 240) ----------------
__device__ __forceinline__ void gate_gemm(int t,
    const float* __restrict__ Wf, const float* __restrict__ Wi,
    const float* __restrict__ Wo, const float* __restrict__ Wc,
    const float* __restrict__ outp, const float* __restrict__ spk,
    const float* __restrict__ pos,
    float (*As)[68], float (*Ws)[260], int tx, int ty)
{
    const int tid = threadIdx.x;
    const int w = blockIdx.x;
    if (w >= 16 * KS_GATE) return;
    const int nt = w / KS_GATE;
    const int ks = w % KS_GATE;
    const int Nbase = nt * 256;
    const int gate = Nbase >> 10;
    const float* W = (gate == 0) ? Wf : (gate == 1) ? Wi : (gate == 2) ? Wo : Wc;
    const int wrow = Nbase & 1023;
    const int k0 = ks * 240;

    ull acc[8][4];
#pragma unroll
    for (int i = 0; i < 8; i++)
#pragma unroll
        for (int j = 0; j < 4; j++) acc[i][j] = 0ull;

    float va[4], vw[16];
#pragma unroll
    for (int p = 0; p < 4; p++) {
        int i = tid + p * 256;
        int m = i >> 4, kg = k0 + (i & 15);
        float v = 0.f;
        if (kg < 1024)      v = g_mem[((size_t)t * BB + m) * HH + kg];
        else if (kg < 2048) v = outp[((size_t)m * SS + (t - 1)) * HH + (kg - 1024)];
        else if (kg < 2064) v = spk[((size_t)m * SS + t) * SPKD + (kg - 2048)];
        else if (kg < 2080) v = pos[((size_t)m * SS + t) * SPKD + (kg - 2064)];
        va[p] = v;
    }
#pragma unroll
    for (int p = 0; p < 16; p++) {
        int i = tid + p * 256;
        int n = i >> 4, kg = k0 + (i & 15);
        vw[p] = (kg < GINK) ? W[(size_t)(wrow + n) * GINK + kg] : 0.f;
    }

    for (int kt = k0; kt < k0 + 240; kt += 16) {
        __syncthreads();
#pragma unroll
        for (int p = 0; p < 4; p++) {
            int i = tid + p * 256;
            As[i & 15][i >> 4] = va[p];
        }
#pragma unroll
        for (int p = 0; p < 16; p++) {
            int i = tid + p * 256;
            Ws[i & 15][i >> 4] = vw[p];
        }
        __syncthreads();
        if (kt + 16 < k0 + 240) {
#pragma unroll
            for (int p = 0; p < 4; p++) {
                int i = tid + p * 256;
                int m = i >> 4, kg = kt + 16 + (i & 15);
                float v = 0.f;
                if (kg < 1024)      v = g_mem[((size_t)t * BB + m) * HH + kg];
                else if (kg < 2048) v = outp[((size_t)m * SS + (t - 1)) * HH + (kg - 1024)];
                else if (kg < 2064) v = spk[((size_t)m * SS + t) * SPKD + (kg - 2048)];
                else if (kg < 2080) v = pos[((size_t)m * SS + t) * SPKD + (kg - 2064)];
                va[p] = v;
            }
#pragma unroll
            for (int p = 0; p < 16; p++) {
                int i = tid + p * 256;
                int n = i >> 4, kg = kt + 16 + (i & 15);
                vw[p] = (kg < GINK) ? W[(size_t)(wrow + n) * GINK + kg] : 0.f;
            }
        }
        mk64(acc, (const float (*)[68])As, (const float (*)[260])Ws, tx, ty);
    }
#pragma unroll
    for (int i2 = 0; i2 < 8; i2++) {
        int m = ty * 8 + i2;
        size_t rowb = ((size_t)ks * BB + m) * 4096;
#pragma unroll
        for (int jp = 0; jp < 4; jp++) {
            int col = Nbase + 2 * tx + 64 * jp;
            F2U u; u.u = acc[i2][jp];
            *(float2*)&g_gpre[rowb + col] = u.f;
        }
    }
}

// ---------------- persistent gating kernel: 512 steps ----------------
__global__ __launch_bounds__(NTHR, 1) void gating_persistent(
    const float* __restrict__ spk, const float* __restrict__ pos,
    const float* __restrict__ Wfw, const float* __restrict__ bfb,
    const float* __restrict__ Wiw, const float* __restrict__ bib,
    const float* __restrict__ Wow, const float* __restrict__ bob,
    const float* __restrict__ Wcw, const float* __restrict__ bcb,
    const float* __restrict__ W1e, const float* __restrict__ b1e,
    const float* __restrict__ gln, const float* __restrict__ beta,
    const float* __restrict__ W2e, const float* __restrict__ b2e,
    float* __restrict__ out)
{
    __shared__ __align__(16) float As[16][68];
    __shared__ __align__(16) float Ws[16][260];
    __shared__ float sred[NTHR];
    __shared__ float stats[2];
    const int tid = threadIdx.x;
    const int tx = tid & 31, ty = tid >> 5;
    const int bx = blockIdx.x;
    unsigned int bar_id = 0;

    for (int t = 0; t < SS; t++) {
        if (t > 0) {
            // --- phase 1: gate GEMM partials ---
            gate_gemm(t, Wfw, Wiw, Wow, Wcw, out, spk, pos, As, Ws, tx, ty);
            gsync(bar_id);
            // --- phase 2: gate combine -> g_gated ---
            for (int e = bx * NTHR + tid; e < BB * HH; e += NBLK * NTHR) {
                int b = e >> 10, i = e & 1023;
                float f = bfb[i], ig = bib[i], o = bob[i], c = bcb[i];
#pragma unroll
                for (int q = 0; q < KS_GATE; q++) {
                    size_t base = ((size_t)q * BB + b) * 4096;
                    f  += g_gpre[base + i];
                    ig += g_gpre[base + 1024 + i];
                    o  += g_gpre[base + 2048 + i];
                    c  += g_gpre[base + 3072 + i];
                }
                float prev = out[((size_t)b * SS + (t - 1)) * HH + i];
                f = sigm(f); ig = sigm(ig); o = sigm(o); c = tanhf(c);
                g_gated[e] = o * tanhf(f * prev + ig * c);
            }
            gsync(bar_id);
        }

        // --- phase 3: emo GEMM1 partials ---
        emo_gemm<0>(t, W1e, g_h1p, As, Ws, tx, ty);
        gsync(bar_id);

        // --- phase 4: LayerNorm + ReLU (64 rows, blocks 0..63) ---
        if (bx < BB) {
            const int b = bx;
            float v[4];
            float lsum = 0.f, lsq = 0.f;
#pragma unroll
            for (int j = 0; j < 4; j++) {
                int i = tid + j * NTHR;
                float x = b1e[i];
#pragma unroll
                for (int q = 0; q < KS_EMO; q++) x += g_h1p[((size_t)q * BB + b) * HH + i];
                v[j] = x; lsum += x; lsq += x * x;
            }
            sred[tid] = lsum; __syncthreads();
            for (int s2 = NTHR / 2; s2 > 0; s2 >>= 1) {
                if (tid < s2) sred[tid] += sred[tid + s2];
                __syncthreads();
            }
            if (tid == 0) stats[0] = sred[0] * (1.f / 1024.f);
            __syncthreads();
            sred[tid] = lsq; __syncthreads();
            for (int s2 = NTHR / 2; s2 > 0; s2 >>= 1) {
                if (tid < s2) sred[tid] += sred[tid + s2];
                __syncthreads();
            }
            if (tid == 0) stats[1] = sred[0] * (1.f / 1024.f);
            __syncthreads();
            float mu = stats[0];
            float var = stats[1] - mu * mu;
            float rs = rsqrtf(var + 1e-5f);
#pragma unroll
            for (int j = 0; j < 4; j++) {
                int i = tid + j * NTHR;
                float y = (v[j] - mu) * rs * gln[i] + beta[i];
                g_hln[(size_t)b * HH + i] = y > 0.f ? y : 0.f;
            }
        }
        gsync(bar_id);

        // --- phase 5: emo GEMM2 partials ---
        emo_gemm<1>(t, W2e, g_o2p, As, Ws, tx, ty);
        gsync(bar_id);

        // --- phase 6: finalize out[t] = sum partials + b2e + residual ---
        for (int e = bx * NTHR + tid; e < BB * HH; e += NBLK * NTHR) {
            int b = e >> 10, i = e & 1023;
            float x = b2e[i];
#pragma unroll
            for (int q = 0; q < KS_EMO; q++) x += g_o2p[((size_t)q * BB + b) * HH + i];
            float res = (t == 0) ? g_mem[(size_t)b * HH + i] : g_gated[e];
            out[((size_t)b * SS + t) * HH + i] = x + res;
        }
        gsync(bar_id);
    }
}

// ---------------- host launcher: 5 graph nodes total ----------------
extern "C" void kernel_launch(void* const* d_in, const int* in_sizes, int n_in,
                              void* d_out, int out_size)
{
    (void)in_sizes; (void)n_in; (void)out_size;
    const float* uf    = (const float*)d_in[0];
    const float* spk   = (const float*)d_in[1];
    const float* pos   = (const float*)d_in[2];
    const float* Wih_f = (const float*)d_in[3];
    const float* Whh_f = (const float*)d_in[4];
    const float* bih_f = (const float*)d_in[5];
    const float* bhh_f = (const float*)d_in[6];
    const float* Wih_b = (const float*)d_in[7];
    const float* Whh_b = (const float*)d_in[8];
    const float* bih_b = (const float*)d_in[9];
    const float* bhh_b = (const float*)d_in[10];
    const float* Wfw   = (const float*)d_in[11];
    const float* bfb   = (const float*)d_in[12];
    const float* Wiw   = (const float*)d_in[13];
    const float* bib   = (const float*)d_in[14];
    const float* Wow   = (const float*)d_in[15];
    const float* bob   = (const float*)d_in[16];
    const float* Wcw   = (const float*)d_in[17];
    const float* bcb   = (const float*)d_in[18];
    const float* W1e   = (const float*)d_in[19];
    const float* b1e   = (const float*)d_in[20];
    const float* g_ln  = (const float*)d_in[21];
    const float* beta  = (const float*)d_in[22];
    const float* W2e   = (const float*)d_in[23];
    const float* b2e   = (const float*)d_in[24];
    float* out = (float*)d_out;

    // 1) x projections for both GRU directions (parallel, big grid)
    xproj_kernel<<<dim3(256, 12, 2), 256>>>(uf, Wih_f, bih_f, Wih_b, bih_b);

    // 2) persistent bidirectional GRU recurrence
    reset_bar_k<<<1, 1>>>();
    gru_persistent<<<NBLK, NTHR>>>(Whh_f, Whh_b, bhh_f, bhh_b);

    // 3) persistent dialogue gating loop
    reset_bar_k<<<1, 1>>>();
    gating_persistent<<<NBLK, NTHR>>>(spk, pos, Wfw, bfb, Wiw, bib, Wow, bob,
                                      Wcw, bcb, W1e, b1e, g_ln, beta, W2e, b2e, out);
}